// round 12
// baseline (speedup 1.0000x reference)
#include <cuda_runtime.h>
#include <stdint.h>

#define Nn   50000
#define Ee   800000
#define FIN  165
#define HID  128
#define NCLS 2

#define BM 128
#define BN 128
#define BK 16

// ---------------- scratch (device globals; 16B-aligned for vector access) ---
__device__ __align__(16) float g_Y[(size_t)Nn * 384];   // fused GEMM out [N,3H]
__device__ __align__(16) float g_U[(size_t)Nn * HID];   // U = Y1 + 2*P(Y2)
__device__ __align__(16) float g_H[(size_t)Nn * HID];   // layer activation
__device__ __align__(16) float g_Y3[Nn * 8];            // layer-3 GEMM out [N,8] (6 used)
__device__ __align__(16) float g_U2[Nn * 2];
__device__ __align__(16) float g_Wcat[FIN * 384];       // concatenated weights
__device__ int   g_row[Ee];     // normalized edge_index row (int32)
__device__ int   g_col[Ee];     // normalized edge_index col (int32)
__device__ int   g_isI64;       // detected input dtype flag
__device__ int   g_deg[Nn];
__device__ float g_dinv[Nn];
__device__ int   g_rowStart[Nn];
__device__ int   g_writePos[Nn];
__device__ int   g_csrCol[Ee];
__device__ float g_csrW[Ee];
__device__ int   g_blockSums[64];
__device__ int   g_blockOffs[64];

// ---------------- packed f32x2 helpers (sm_100+) ----------------------------
__device__ __forceinline__ void ffma2(unsigned long long& d,
                                      unsigned long long a,
                                      unsigned long long b) {
    asm("fma.rn.f32x2 %0, %1, %2, %0;" : "+l"(d) : "l"(a), "l"(b));
}
__device__ __forceinline__ unsigned long long splat2(float x) {
    unsigned long long r;
    asm("mov.b64 %0, {%1, %1};" : "=l"(r) : "r"(__float_as_uint(x)));
    return r;
}

// ---------------- cp.async helpers ------------------------------------------
__device__ __forceinline__ void cpa4(void* smem, const void* g, bool p) {
    uint32_t sa = (uint32_t)__cvta_generic_to_shared(smem);
    int sz = p ? 4 : 0;   // src-size 0 -> zero-fill
    asm volatile("cp.async.ca.shared.global [%0], [%1], 4, %2;\n"
                 :: "r"(sa), "l"(g), "r"(sz));
}
__device__ __forceinline__ void cpa16(void* smem, const void* g, bool p) {
    uint32_t sa = (uint32_t)__cvta_generic_to_shared(smem);
    int sz = p ? 16 : 0;
    asm volatile("cp.async.cg.shared.global [%0], [%1], 16, %2;\n"
                 :: "r"(sa), "l"(g), "r"(sz));
}
#define CP_COMMIT() asm volatile("cp.async.commit_group;\n" ::)
template<int N>
__device__ __forceinline__ void cp_wait() {
    asm volatile("cp.async.wait_group %0;\n" :: "n"(N));
}

// ---------------- dtype detection + normalization ---------------------------
__global__ void k_detect(const int* __restrict__ w) {   // 1 block, 512 threads
    __shared__ int nz;
    if (threadIdx.x == 0) nz = 0;
    __syncthreads();
    int v = w[2 * threadIdx.x + 1];
    if (v != 0) nz = 1;               // benign race
    __syncthreads();
    if (threadIdx.x == 0) g_isI64 = (nz == 0) ? 1 : 0;
}

// normalize + degree count fused (g_deg must be zeroed first)
__global__ void k_norm(const void* __restrict__ ei) {
    int e = blockIdx.x * blockDim.x + threadIdx.x;
    if (e >= Ee) return;
    int r, c;
    if (g_isI64) {
        r = (int)((const long long*)ei)[e];
        c = (int)((const long long*)ei)[Ee + e];
    } else {
        r = ((const int*)ei)[e];
        c = ((const int*)ei)[Ee + e];
    }
    g_row[e] = r;
    g_col[e] = c;
    if ((unsigned)r < Nn && (unsigned)c < Nn)
        atomicAdd(&g_deg[r], 1);
}

// ---------------- graph preprocessing --------------------------------------
__global__ void k_zero_deg() {
    int i = blockIdx.x * blockDim.x + threadIdx.x;
    if (i < Nn) g_deg[i] = 0;
}

__global__ void k_scan_blocks() {   // grid=49, block=1024
    __shared__ int s[1024];
    int i = blockIdx.x * 1024 + threadIdx.x;
    int v = (i < Nn) ? g_deg[i] : 0;
    s[threadIdx.x] = v;
    __syncthreads();
    for (int off = 1; off < 1024; off <<= 1) {
        int t = (threadIdx.x >= off) ? s[threadIdx.x - off] : 0;
        __syncthreads();
        s[threadIdx.x] += t;
        __syncthreads();
    }
    if (i < Nn) g_rowStart[i] = s[threadIdx.x] - v;
    if (threadIdx.x == 1023) g_blockSums[blockIdx.x] = s[1023];
}

__global__ void k_scan_partials(int nb) {   // 1 block, 64 threads
    __shared__ int s[64];
    int v = (threadIdx.x < nb) ? g_blockSums[threadIdx.x] : 0;
    s[threadIdx.x] = v;
    __syncthreads();
    for (int off = 1; off < 64; off <<= 1) {
        int t = (threadIdx.x >= off) ? s[threadIdx.x - off] : 0;
        __syncthreads();
        s[threadIdx.x] += t;
        __syncthreads();
    }
    if (threadIdx.x < nb) g_blockOffs[threadIdx.x] = s[threadIdx.x] - v;
}

__global__ void k_add_offsets() {
    int i = blockIdx.x * blockDim.x + threadIdx.x;
    if (i < Nn) {
        int rs = g_rowStart[i] + g_blockOffs[i >> 10];
        g_rowStart[i] = rs;
        g_writePos[i] = rs;
        int d = g_deg[i];
        g_dinv[i] = (d > 0) ? rsqrtf((float)d) : 0.0f;
    }
}

__global__ void k_fill() {
    int e = blockIdx.x * blockDim.x + threadIdx.x;
    if (e < Ee) {
        int r = g_row[e], c = g_col[e];
        if ((unsigned)r < Nn && (unsigned)c < Nn) {
            float w = -g_dinv[r] * g_dinv[c];
            int p = atomicAdd(&g_writePos[r], 1);
            g_csrCol[p] = c;
            g_csrW[p]   = w;
        }
    }
}

// ---------------- weight concat: Wcat[i, k*128+j] = W[k, i, j] --------------
__global__ void k_wcat(const float* __restrict__ W, int fin) {
    int idx = blockIdx.x * blockDim.x + threadIdx.x;
    int tot = fin * 384;
    if (idx < tot) {
        int i = idx / 384, c = idx % 384;
        int k = c >> 7, j = c & 127;
        g_Wcat[idx] = W[((size_t)k * fin + i) * 128 + j];
    }
}

// ---------------- SGEMM: g_Y[M,384] = A[M,K] @ g_Wcat[K,384] -----------------
// 128x128 tile, BK=16, 256 threads, 8x8 microtile, packed FFMA2 math.
// Tile loads via cp.async (no staging registers, zfill for bounds/tails);
// double-buffered with commit/wait_group. __launch_bounds__(256,2) keeps
// 2 CTAs/SM; without staging regs the natural count fits under 128 (no spill).
template<int KVAL, bool FROMH>
__global__ void __launch_bounds__(256, 2)
k_sgemm_t(const float* __restrict__ Aext) {
    constexpr int M = Nn;
    constexpr int NT = (KVAL + BK - 1) / BK;
    __shared__ float As[2][BK][BM];
    __shared__ float Bs[2][BK][BN];
    const float* A = FROMH ? (const float*)g_H : Aext;

    int tid = threadIdx.x;
    int tx = tid & 15, ty = tid >> 4;
    int rowBase = blockIdx.x * BM;
    int colBase = blockIdx.y * BN;

    unsigned long long acc[8][4];
    #pragma unroll
    for (int i = 0; i < 8; i++)
        #pragma unroll
        for (int j = 0; j < 4; j++) acc[i][j] = 0ull;

    // issue async copies for k-tile t into buffer s
    auto issueTile = [&](int t, int s) {
        int k0 = t * BK;
        // A: 4B-granular (k-major smem layout scatters row fragments)
        #pragma unroll
        for (int q = 0; q < 8; q++) {
            int linear = tid * 8 + q;
            int kk = linear & 15;
            int r  = linear >> 4;
            int grow = rowBase + r;
            int gk = k0 + kk;
            bool p = (grow < M) && (gk < KVAL);
            const float* gp = p ? (A + (size_t)grow * KVAL + gk) : A;
            cpa4(&As[s][kk][r], gp, p);
        }
        // B: 16B chunks (contiguous in both global and smem)
        #pragma unroll
        for (int i = 0; i < 2; i++) {
            int idx = tid + i * 256;
            int kk = idx >> 5;
            int cv = (idx & 31) << 2;
            int gk = k0 + kk;
            bool p = (gk < KVAL);
            const float* gp = p ? &g_Wcat[gk * 384 + colBase + cv] : g_Wcat;
            cpa16(&Bs[s][kk][cv], gp, p);
        }
    };

    issueTile(0, 0);
    CP_COMMIT();

    for (int t = 0; t < NT; t++) {
        int s = t & 1;
        if (t + 1 < NT) {
            issueTile(t + 1, s ^ 1);
            CP_COMMIT();
            cp_wait<1>();          // tile t complete (t+1 may remain in flight)
        } else {
            cp_wait<0>();
        }
        __syncthreads();
        #pragma unroll
        for (int kk = 0; kk < BK; kk++) {
            float ra[8];
            *(float4*)&ra[0] = *(const float4*)&As[s][kk][ty * 8];
            *(float4*)&ra[4] = *(const float4*)&As[s][kk][ty * 8 + 4];
            ulonglong2 rb0 = *(const ulonglong2*)&Bs[s][kk][tx * 4];       // cols tx*4..+3
            ulonglong2 rb1 = *(const ulonglong2*)&Bs[s][kk][64 + tx * 4];  // cols 64+tx*4..+3
            #pragma unroll
            for (int i = 0; i < 8; i++) {
                unsigned long long a2 = splat2(ra[i]);
                ffma2(acc[i][0], a2, rb0.x);
                ffma2(acc[i][1], a2, rb0.y);
                ffma2(acc[i][2], a2, rb1.x);
                ffma2(acc[i][3], a2, rb1.y);
            }
        }
        __syncthreads();           // buffer s reusable for tile t+2
    }

    #pragma unroll
    for (int i = 0; i < 8; i++) {
        int row = rowBase + ty * 8 + i;
        if (row < M) {
            float* dst = &g_Y[(size_t)row * 384 + colBase];
            ulonglong2 o0; o0.x = acc[i][0]; o0.y = acc[i][1];
            ulonglong2 o1; o1.x = acc[i][2]; o1.y = acc[i][3];
            *(ulonglong2*)&dst[tx * 4]      = o0;   // 16B-aligned (colBase%128==0)
            *(ulonglong2*)&dst[64 + tx * 4] = o1;
        }
    }
}

// ---------------- propagation (warp per node, 128-wide) ---------------------
__device__ __forceinline__ float4 gather_row(const float* __restrict__ src,
                                             int srcStride, int srcOff,
                                             int start, int d, int lane) {
    float4 acc = make_float4(0.f, 0.f, 0.f, 0.f);
    int j = 0;
    for (; j + 32 <= d; j += 32) {
        int   cc0 = __ldg(&g_csrCol[start + j + lane]);
        float ww0 = __ldg(&g_csrW[start + j + lane]);
        #pragma unroll 4
        for (int k = 0; k < 32; k++) {
            int   cc = __shfl_sync(0xffffffffu, cc0, k);
            float ww = __shfl_sync(0xffffffffu, ww0, k);
            float4 v = *(const float4*)&src[(size_t)cc * srcStride + srcOff + (lane << 2)];
            acc.x = fmaf(ww, v.x, acc.x);
            acc.y = fmaf(ww, v.y, acc.y);
            acc.z = fmaf(ww, v.z, acc.z);
            acc.w = fmaf(ww, v.w, acc.w);
        }
    }
    int rem = d - j;
    if (rem > 0) {
        int idx = j + lane;
        int cc0 = 0; float ww0 = 0.f;
        if (idx < d) { cc0 = __ldg(&g_csrCol[start + idx]); ww0 = __ldg(&g_csrW[start + idx]); }
        for (int k = 0; k < rem; k++) {
            int   cc = __shfl_sync(0xffffffffu, cc0, k);
            float ww = __shfl_sync(0xffffffffu, ww0, k);
            float4 v = *(const float4*)&src[(size_t)cc * srcStride + srcOff + (lane << 2)];
            acc.x = fmaf(ww, v.x, acc.x);
            acc.y = fmaf(ww, v.y, acc.y);
            acc.z = fmaf(ww, v.z, acc.z);
            acc.w = fmaf(ww, v.w, acc.w);
        }
    }
    return acc;
}

__global__ void __launch_bounds__(256) k_propA() {
    int gw = (blockIdx.x * blockDim.x + threadIdx.x) >> 5;
    if (gw >= Nn) return;
    int lane  = threadIdx.x & 31;
    int start = g_rowStart[gw];
    int d     = g_deg[gw];
    float4 acc = gather_row(g_Y, 384, 256, start, d, lane);
    float4 y1 = *(const float4*)&g_Y[(size_t)gw * 384 + 128 + (lane << 2)];
    float4 o  = make_float4(fmaf(2.f, acc.x, y1.x), fmaf(2.f, acc.y, y1.y),
                            fmaf(2.f, acc.z, y1.z), fmaf(2.f, acc.w, y1.w));
    *(float4*)&g_U[(size_t)gw * 128 + (lane << 2)] = o;
}

__global__ void __launch_bounds__(256) k_propB(const float* __restrict__ bias) {
    int gw = (blockIdx.x * blockDim.x + threadIdx.x) >> 5;
    if (gw >= Nn) return;
    int lane  = threadIdx.x & 31;
    int start = g_rowStart[gw];
    int d     = g_deg[gw];
    float4 acc = gather_row(g_U, 128, 0, start, d, lane);
    float4 y0 = *(const float4*)&g_Y[(size_t)gw * 384 + (lane << 2)];
    float4 y2 = *(const float4*)&g_Y[(size_t)gw * 384 + 256 + (lane << 2)];
    int lb = lane << 2;
    float b0 = bias[lb], b1v = bias[lb + 1], b2v = bias[lb + 2], b3v = bias[lb + 3];
    float4 o;
    o.x = fminf(fmaxf(y0.x - y2.x + acc.x + b0,  0.f), 6.f);
    o.y = fminf(fmaxf(y0.y - y2.y + acc.y + b1v, 0.f), 6.f);
    o.z = fminf(fmaxf(y0.z - y2.z + acc.z + b2v, 0.f), 6.f);
    o.w = fminf(fmaxf(y0.w - y2.w + acc.w + b3v, 0.f), 6.f);
    *(float4*)&g_H[(size_t)gw * 128 + (lane << 2)] = o;
}

// ---------------- layer 3 (128 -> 6 fused, then 2-wide props) ---------------
__global__ void k_gemm3(const float* __restrict__ W3) {
    __shared__ float ws[128 * 6];
    int tid = threadIdx.x;
    for (int idx = tid; idx < 768; idx += blockDim.x) {
        int i = idx / 6, c = idx % 6;
        ws[idx] = W3[(c >> 1) * 256 + i * 2 + (c & 1)];
    }
    __syncthreads();
    int node = blockIdx.x * blockDim.x + tid;
    if (node >= Nn) return;
    float acc[8] = {0, 0, 0, 0, 0, 0, 0, 0};
    const float* hr = &g_H[(size_t)node * 128];
    #pragma unroll 8
    for (int i = 0; i < 128; i++) {
        float h = hr[i];
        #pragma unroll
        for (int c = 0; c < 6; c++)
            acc[c] = fmaf(h, ws[i * 6 + c], acc[c]);
    }
    #pragma unroll
    for (int c = 0; c < 8; c++) g_Y3[node * 8 + c] = acc[c];
}

__global__ void k_propA3() {
    int i = blockIdx.x * blockDim.x + threadIdx.x;
    if (i >= Nn) return;
    int start = g_rowStart[i], d = g_deg[i];
    float a0 = 0.f, a1 = 0.f;
    for (int e = 0; e < d; e++) {
        int   c = __ldg(&g_csrCol[start + e]);
        float w = __ldg(&g_csrW[start + e]);
        a0 = fmaf(w, g_Y3[c * 8 + 4], a0);
        a1 = fmaf(w, g_Y3[c * 8 + 5], a1);
    }
    g_U2[i * 2]     = g_Y3[i * 8 + 2] + 2.f * a0;
    g_U2[i * 2 + 1] = g_Y3[i * 8 + 3] + 2.f * a1;
}

__global__ void k_propB3(const float* __restrict__ b3, float* __restrict__ out) {
    int i = blockIdx.x * blockDim.x + threadIdx.x;
    if (i >= Nn) return;
    int start = g_rowStart[i], d = g_deg[i];
    float a0 = 0.f, a1 = 0.f;
    for (int e = 0; e < d; e++) {
        int   c = __ldg(&g_csrCol[start + e]);
        float w = __ldg(&g_csrW[start + e]);
        a0 = fmaf(w, g_U2[c * 2],     a0);
        a1 = fmaf(w, g_U2[c * 2 + 1], a1);
    }
    out[i * 2]     = g_Y3[i * 8 + 0] - g_Y3[i * 8 + 4] + a0 + b3[0];
    out[i * 2 + 1] = g_Y3[i * 8 + 1] - g_Y3[i * 8 + 5] + a1 + b3[1];
}

// ---------------- output tail (edge_index passthrough) ----------------------
__global__ void k_tail_i64(long long* __restrict__ dst) {
    int i = blockIdx.x * blockDim.x + threadIdx.x;
    if (i < 2 * Ee) dst[i] = (long long)(i < Ee ? g_row[i] : g_col[i - Ee]);
}

__global__ void k_tail_f32(float* __restrict__ dst, int n) {
    int i = blockIdx.x * blockDim.x + threadIdx.x;
    if (i < n) dst[i] = (float)(i < Ee ? g_row[i] : g_col[i - Ee]);
}

// ---------------- launcher ---------------------------------------------------
extern "C" void kernel_launch(void* const* d_in, const int* in_sizes, int n_in,
                              void* d_out, int out_size) {
    const float* x  = (const float*)d_in[0];
    const void*  ei = d_in[1];
    const float* W1 = (const float*)d_in[2];
    const float* b1 = (const float*)d_in[3];
    const float* W2 = (const float*)d_in[4];
    const float* b2 = (const float*)d_in[5];
    const float* W3 = (const float*)d_in[6];
    const float* b3 = (const float*)d_in[7];

    const int gN = (Nn + 255) / 256;
    const int gE = (Ee + 255) / 256;
    const int gW = (Nn * 32 + 255) / 256;   // warp-per-node kernels
    dim3 gg((Nn + BM - 1) / BM, 384 / BN);  // (391, 3)

    // --- dtype detection + normalization (degree count fused into k_norm)
    k_detect<<<1, 512>>>((const int*)ei);                       // 0
    k_zero_deg<<<gN, 256>>>();                                  // 1
    k_norm<<<gE, 256>>>(ei);                                    // 2
    k_wcat<<<(FIN * 384 + 255) / 256, 256>>>(W1, FIN);          // 3
    k_sgemm_t<FIN, false><<<gg, 256>>>(x);                      // 4

    // --- graph preprocessing: scan, dinv, CSR fill
    k_scan_blocks<<<49, 1024>>>();
    k_scan_partials<<<1, 64>>>(49);
    k_add_offsets<<<gN, 256>>>();
    k_fill<<<gE, 256>>>();

    // --- layer 1 props: H = relu6(Y0 - Y2 + P(Y1 + 2 P Y2) + b1)
    k_propA<<<gW, 256>>>();
    k_propB<<<gW, 256>>>(b1);

    // --- layer 2
    k_wcat<<<(HID * 384 + 255) / 256, 256>>>(W2, HID);
    k_sgemm_t<HID, true><<<gg, 256>>>(nullptr);
    k_propA<<<gW, 256>>>();
    k_propB<<<gW, 256>>>(b2);

    // --- layer 3 (no activation)
    k_gemm3<<<(Nn + 255) / 256, 256>>>(W3);
    k_propA3<<<gN, 256>>>();
    k_propB3<<<gN, 256>>>(b3, (float*)d_out);

    // --- edge_index passthrough into the tail of d_out, if present
    long long head = (long long)Nn * NCLS;            // 100000 fp32 elems
    long long tail = (long long)out_size - head;
    if (tail >= 2LL * 2 * Ee) {
        k_tail_i64<<<(2 * Ee + 255) / 256, 256>>>(
            (long long*)((float*)d_out + head));
    } else if (tail > 0) {
        int n = (int)(tail < 2LL * Ee ? tail : 2LL * Ee);
        k_tail_f32<<<(n + 255) / 256, 256>>>((float*)d_out + head, n);
    }
}

// round 13
// speedup vs baseline: 1.0908x; 1.0908x over previous
#include <cuda_runtime.h>
#include <cuda_fp16.h>
#include <stdint.h>

#define Nn   50000
#define Ee   800000
#define FIN  165
#define HID  128
#define NCLS 2

#define BM 128
#define BN 128
#define BK 16

// ---------------- scratch (device globals; 16B-aligned for vector access) ---
__device__ __align__(16) float  g_Y[(size_t)Nn * 384];   // fused GEMM out [N,3H]
__device__ __align__(16) __half g_Uh[(size_t)Nn * HID];  // U = Y1 + 2*P(Y2), fp16
__device__ __align__(16) float  g_H[(size_t)Nn * HID];   // layer activation
__device__ __align__(16) float  g_Y3[Nn * 8];            // layer-3 GEMM out [N,8]
__device__ __align__(16) float  g_U2[Nn * 2];
__device__ __align__(16) float  g_Wcat[FIN * 384];       // concatenated weights
__device__ int   g_row[Ee];
__device__ int   g_col[Ee];
__device__ int   g_isI64;
__device__ int   g_deg[Nn];
__device__ float g_dinv[Nn];
__device__ int   g_rowStart[Nn];
__device__ int   g_writePos[Nn];
__device__ int   g_csrCol[Ee];
__device__ float g_csrW[Ee];
__device__ int   g_blockSums[64];
__device__ int   g_blockOffs[64];

// ---------------- packed f32x2 helpers (sm_100+) ----------------------------
__device__ __forceinline__ void ffma2(unsigned long long& d,
                                      unsigned long long a,
                                      unsigned long long b) {
    asm("fma.rn.f32x2 %0, %1, %2, %0;" : "+l"(d) : "l"(a), "l"(b));
}
__device__ __forceinline__ unsigned long long splat2(float x) {
    unsigned long long r;
    asm("mov.b64 %0, {%1, %1};" : "=l"(r) : "r"(__float_as_uint(x)));
    return r;
}

// ---------------- dtype detection + normalization ---------------------------
__global__ void k_detect(const int* __restrict__ w) {   // 1 block, 512 threads
    __shared__ int nz;
    if (threadIdx.x == 0) nz = 0;
    __syncthreads();
    int v = w[2 * threadIdx.x + 1];
    if (v != 0) nz = 1;               // benign race
    __syncthreads();
    if (threadIdx.x == 0) g_isI64 = (nz == 0) ? 1 : 0;
}

// normalize + degree count fused (g_deg must be zeroed first)
__global__ void k_norm(const void* __restrict__ ei) {
    int e = blockIdx.x * blockDim.x + threadIdx.x;
    if (e >= Ee) return;
    int r, c;
    if (g_isI64) {
        r = (int)((const long long*)ei)[e];
        c = (int)((const long long*)ei)[Ee + e];
    } else {
        r = ((const int*)ei)[e];
        c = ((const int*)ei)[Ee + e];
    }
    g_row[e] = r;
    g_col[e] = c;
    if ((unsigned)r < Nn && (unsigned)c < Nn)
        atomicAdd(&g_deg[r], 1);
}

// ---------------- graph preprocessing --------------------------------------
__global__ void k_zero_deg() {
    int i = blockIdx.x * blockDim.x + threadIdx.x;
    if (i < Nn) g_deg[i] = 0;
}

__global__ void k_scan_blocks() {   // grid=49, block=1024
    __shared__ int s[1024];
    int i = blockIdx.x * 1024 + threadIdx.x;
    int v = (i < Nn) ? g_deg[i] : 0;
    s[threadIdx.x] = v;
    __syncthreads();
    for (int off = 1; off < 1024; off <<= 1) {
        int t = (threadIdx.x >= off) ? s[threadIdx.x - off] : 0;
        __syncthreads();
        s[threadIdx.x] += t;
        __syncthreads();
    }
    if (i < Nn) g_rowStart[i] = s[threadIdx.x] - v;
    if (threadIdx.x == 1023) g_blockSums[blockIdx.x] = s[1023];
}

__global__ void k_scan_partials(int nb) {   // 1 block, 64 threads
    __shared__ int s[64];
    int v = (threadIdx.x < nb) ? g_blockSums[threadIdx.x] : 0;
    s[threadIdx.x] = v;
    __syncthreads();
    for (int off = 1; off < 64; off <<= 1) {
        int t = (threadIdx.x >= off) ? s[threadIdx.x - off] : 0;
        __syncthreads();
        s[threadIdx.x] += t;
        __syncthreads();
    }
    if (threadIdx.x < nb) g_blockOffs[threadIdx.x] = s[threadIdx.x] - v;
}

__global__ void k_add_offsets() {
    int i = blockIdx.x * blockDim.x + threadIdx.x;
    if (i < Nn) {
        int rs = g_rowStart[i] + g_blockOffs[i >> 10];
        g_rowStart[i] = rs;
        g_writePos[i] = rs;
        int d = g_deg[i];
        g_dinv[i] = (d > 0) ? rsqrtf((float)d) : 0.0f;
    }
}

__global__ void k_fill() {
    int e = blockIdx.x * blockDim.x + threadIdx.x;
    if (e < Ee) {
        int r = g_row[e], c = g_col[e];
        if ((unsigned)r < Nn && (unsigned)c < Nn) {
            float w = -g_dinv[r] * g_dinv[c];
            int p = atomicAdd(&g_writePos[r], 1);
            g_csrCol[p] = c;
            g_csrW[p]   = w;
        }
    }
}

// ---------------- weight concat: Wcat[i, k*128+j] = W[k, i, j] --------------
__global__ void k_wcat(const float* __restrict__ W, int fin) {
    int idx = blockIdx.x * blockDim.x + threadIdx.x;
    int tot = fin * 384;
    if (idx < tot) {
        int i = idx / 384, c = idx % 384;
        int k = c >> 7, j = c & 127;
        g_Wcat[idx] = W[((size_t)k * fin + i) * 128 + j];
    }
}

// ---------------- SGEMM: g_Y[M,384] = A[M,K] @ g_Wcat[K,384] -----------------
// 128x128 tile, BK=16, 256 threads, 8x8 microtile, double-buffered smem with
// register prefetch, packed FFMA2 math. (R10 measured-best configuration.)
template<int KVAL, bool FROMH>
__global__ void __launch_bounds__(256, 2)
k_sgemm_t(const float* __restrict__ Aext) {
    constexpr int M = Nn;
    constexpr int NT = (KVAL + BK - 1) / BK;
    __shared__ float As[2][BK][BM];
    __shared__ float Bs[2][BK][BN];
    const float* A = FROMH ? (const float*)g_H : Aext;

    int tid = threadIdx.x;
    int tx = tid & 15, ty = tid >> 4;
    int rowBase = blockIdx.x * BM;
    int colBase = blockIdx.y * BN;

    unsigned long long acc[8][4];
    #pragma unroll
    for (int i = 0; i < 8; i++)
        #pragma unroll
        for (int j = 0; j < 4; j++) acc[i][j] = 0ull;

    float a_nxt[8];
    float b_nxt[8];

    auto fetchA = [&](int t) {
        int k0 = t * BK;
        if (KVAL == HID) {
            #pragma unroll
            for (int i = 0; i < 2; i++) {
                int idx = tid + i * 256;
                int kk4 = (idx & 3) << 2;
                int r = idx >> 2;
                int grow = rowBase + r;
                float4 v = make_float4(0.f, 0.f, 0.f, 0.f);
                if (grow < M) v = *(const float4*)&A[(size_t)grow * HID + k0 + kk4];
                a_nxt[i * 4 + 0] = v.x; a_nxt[i * 4 + 1] = v.y;
                a_nxt[i * 4 + 2] = v.z; a_nxt[i * 4 + 3] = v.w;
            }
        } else {
            #pragma unroll
            for (int q = 0; q < 8; q++) {
                int linear = tid * 8 + q;
                int kk = linear & 15;
                int r = linear >> 4;
                int grow = rowBase + r;
                int gk = k0 + kk;
                a_nxt[q] = (grow < M && gk < KVAL) ? A[(size_t)grow * KVAL + gk] : 0.f;
            }
        }
    };
    auto storeA = [&](int s) {
        if (KVAL == HID) {
            #pragma unroll
            for (int i = 0; i < 2; i++) {
                int idx = tid + i * 256;
                int kk4 = (idx & 3) << 2;
                int r = idx >> 2;
                As[s][kk4 + 0][r] = a_nxt[i * 4 + 0];
                As[s][kk4 + 1][r] = a_nxt[i * 4 + 1];
                As[s][kk4 + 2][r] = a_nxt[i * 4 + 2];
                As[s][kk4 + 3][r] = a_nxt[i * 4 + 3];
            }
        } else {
            #pragma unroll
            for (int q = 0; q < 8; q++) {
                int linear = tid * 8 + q;
                int kk = linear & 15;
                int r = linear >> 4;
                As[s][kk][r] = a_nxt[q];
            }
        }
    };
    auto fetchB = [&](int t) {
        int k0 = t * BK;
        #pragma unroll
        for (int i = 0; i < 2; i++) {
            int idx = tid + i * 256;
            int kk = idx >> 5;
            int cv = (idx & 31) << 2;
            int gk = k0 + kk;
            float4 v = make_float4(0.f, 0.f, 0.f, 0.f);
            if (gk < KVAL) v = *(const float4*)&g_Wcat[gk * 384 + colBase + cv];
            b_nxt[i * 4 + 0] = v.x; b_nxt[i * 4 + 1] = v.y;
            b_nxt[i * 4 + 2] = v.z; b_nxt[i * 4 + 3] = v.w;
        }
    };
    auto storeB = [&](int s) {
        #pragma unroll
        for (int i = 0; i < 2; i++) {
            int idx = tid + i * 256;
            int kk = idx >> 5;
            int cv = (idx & 31) << 2;
            Bs[s][kk][cv + 0] = b_nxt[i * 4 + 0];
            Bs[s][kk][cv + 1] = b_nxt[i * 4 + 1];
            Bs[s][kk][cv + 2] = b_nxt[i * 4 + 2];
            Bs[s][kk][cv + 3] = b_nxt[i * 4 + 3];
        }
    };

    fetchA(0); fetchB(0);
    storeA(0); storeB(0);
    __syncthreads();

    for (int t = 0; t < NT; t++) {
        int s = t & 1;
        if (t + 1 < NT) { fetchA(t + 1); fetchB(t + 1); }
        #pragma unroll
        for (int kk = 0; kk < BK; kk++) {
            float ra[8];
            *(float4*)&ra[0] = *(const float4*)&As[s][kk][ty * 8];
            *(float4*)&ra[4] = *(const float4*)&As[s][kk][ty * 8 + 4];
            ulonglong2 rb0 = *(const ulonglong2*)&Bs[s][kk][tx * 4];
            ulonglong2 rb1 = *(const ulonglong2*)&Bs[s][kk][64 + tx * 4];
            #pragma unroll
            for (int i = 0; i < 8; i++) {
                unsigned long long a2 = splat2(ra[i]);
                ffma2(acc[i][0], a2, rb0.x);
                ffma2(acc[i][1], a2, rb0.y);
                ffma2(acc[i][2], a2, rb1.x);
                ffma2(acc[i][3], a2, rb1.y);
            }
        }
        if (t + 1 < NT) { storeA(s ^ 1); storeB(s ^ 1); }
        __syncthreads();
    }

    #pragma unroll
    for (int i = 0; i < 8; i++) {
        int row = rowBase + ty * 8 + i;
        if (row < M) {
            float* dst = &g_Y[(size_t)row * 384 + colBase];
            ulonglong2 o0; o0.x = acc[i][0]; o0.y = acc[i][1];
            ulonglong2 o1; o1.x = acc[i][2]; o1.y = acc[i][3];
            *(ulonglong2*)&dst[tx * 4]      = o0;
            *(ulonglong2*)&dst[64 + tx * 4] = o1;
        }
    }
}

// ---------------- propagation (warp per node, 128-wide) ---------------------
// fp32 gather from g_Y (propA source)
__device__ __forceinline__ float4 gather_row(const float* __restrict__ src,
                                             int srcStride, int srcOff,
                                             int start, int d, int lane) {
    float4 acc = make_float4(0.f, 0.f, 0.f, 0.f);
    int j = 0;
    for (; j + 32 <= d; j += 32) {
        int   cc0 = __ldg(&g_csrCol[start + j + lane]);
        float ww0 = __ldg(&g_csrW[start + j + lane]);
        #pragma unroll 4
        for (int k = 0; k < 32; k++) {
            int   cc = __shfl_sync(0xffffffffu, cc0, k);
            float ww = __shfl_sync(0xffffffffu, ww0, k);
            float4 v = *(const float4*)&src[(size_t)cc * srcStride + srcOff + (lane << 2)];
            acc.x = fmaf(ww, v.x, acc.x);
            acc.y = fmaf(ww, v.y, acc.y);
            acc.z = fmaf(ww, v.z, acc.z);
            acc.w = fmaf(ww, v.w, acc.w);
        }
    }
    int rem = d - j;
    if (rem > 0) {
        int idx = j + lane;
        int cc0 = 0; float ww0 = 0.f;
        if (idx < d) { cc0 = __ldg(&g_csrCol[start + idx]); ww0 = __ldg(&g_csrW[start + idx]); }
        for (int k = 0; k < rem; k++) {
            int   cc = __shfl_sync(0xffffffffu, cc0, k);
            float ww = __shfl_sync(0xffffffffu, ww0, k);
            float4 v = *(const float4*)&src[(size_t)cc * srcStride + srcOff + (lane << 2)];
            acc.x = fmaf(ww, v.x, acc.x);
            acc.y = fmaf(ww, v.y, acc.y);
            acc.z = fmaf(ww, v.z, acc.z);
            acc.w = fmaf(ww, v.w, acc.w);
        }
    }
    return acc;
}

// fp16 gather from g_Uh (propB source): 8B per lane instead of 16B
__device__ __forceinline__ float4 gather_row_h(int start, int d, int lane) {
    float4 acc = make_float4(0.f, 0.f, 0.f, 0.f);
    int j = 0;
    for (; j + 32 <= d; j += 32) {
        int   cc0 = __ldg(&g_csrCol[start + j + lane]);
        float ww0 = __ldg(&g_csrW[start + j + lane]);
        #pragma unroll 4
        for (int k = 0; k < 32; k++) {
            int   cc = __shfl_sync(0xffffffffu, cc0, k);
            float ww = __shfl_sync(0xffffffffu, ww0, k);
            uint2 raw = *(const uint2*)&g_Uh[(size_t)cc * HID + (lane << 2)];
            float2 f0 = __half22float2(*reinterpret_cast<__half2*>(&raw.x));
            float2 f1 = __half22float2(*reinterpret_cast<__half2*>(&raw.y));
            acc.x = fmaf(ww, f0.x, acc.x);
            acc.y = fmaf(ww, f0.y, acc.y);
            acc.z = fmaf(ww, f1.x, acc.z);
            acc.w = fmaf(ww, f1.y, acc.w);
        }
    }
    int rem = d - j;
    if (rem > 0) {
        int idx = j + lane;
        int cc0 = 0; float ww0 = 0.f;
        if (idx < d) { cc0 = __ldg(&g_csrCol[start + idx]); ww0 = __ldg(&g_csrW[start + idx]); }
        for (int k = 0; k < rem; k++) {
            int   cc = __shfl_sync(0xffffffffu, cc0, k);
            float ww = __shfl_sync(0xffffffffu, ww0, k);
            uint2 raw = *(const uint2*)&g_Uh[(size_t)cc * HID + (lane << 2)];
            float2 f0 = __half22float2(*reinterpret_cast<__half2*>(&raw.x));
            float2 f1 = __half22float2(*reinterpret_cast<__half2*>(&raw.y));
            acc.x = fmaf(ww, f0.x, acc.x);
            acc.y = fmaf(ww, f0.y, acc.y);
            acc.z = fmaf(ww, f1.x, acc.z);
            acc.w = fmaf(ww, f1.y, acc.w);
        }
    }
    return acc;
}

// propA: U[i,:] = Y[i,128:256] + 2 * sum_e w_e * Y[col_e, 256:384], stored fp16
__global__ void __launch_bounds__(256) k_propA() {
    int gw = (blockIdx.x * blockDim.x + threadIdx.x) >> 5;
    if (gw >= Nn) return;
    int lane  = threadIdx.x & 31;
    int start = g_rowStart[gw];
    int d     = g_deg[gw];
    float4 acc = gather_row(g_Y, 384, 256, start, d, lane);
    float4 y1 = *(const float4*)&g_Y[(size_t)gw * 384 + 128 + (lane << 2)];
    float4 o  = make_float4(fmaf(2.f, acc.x, y1.x), fmaf(2.f, acc.y, y1.y),
                            fmaf(2.f, acc.z, y1.z), fmaf(2.f, acc.w, y1.w));
    __half2 h01 = __floats2half2_rn(o.x, o.y);
    __half2 h23 = __floats2half2_rn(o.z, o.w);
    uint2 st;
    st.x = *reinterpret_cast<uint32_t*>(&h01);
    st.y = *reinterpret_cast<uint32_t*>(&h23);
    *(uint2*)&g_Uh[(size_t)gw * HID + (lane << 2)] = st;
}

// propB: H[i,:] = relu6( Y[i,0:128] - Y[i,256:384] + sum_e w_e * U[col_e,:] + b )
__global__ void __launch_bounds__(256) k_propB(const float* __restrict__ bias) {
    int gw = (blockIdx.x * blockDim.x + threadIdx.x) >> 5;
    if (gw >= Nn) return;
    int lane  = threadIdx.x & 31;
    int start = g_rowStart[gw];
    int d     = g_deg[gw];
    float4 acc = gather_row_h(start, d, lane);
    float4 y0 = *(const float4*)&g_Y[(size_t)gw * 384 + (lane << 2)];
    float4 y2 = *(const float4*)&g_Y[(size_t)gw * 384 + 256 + (lane << 2)];
    int lb = lane << 2;
    float b0 = bias[lb], b1v = bias[lb + 1], b2v = bias[lb + 2], b3v = bias[lb + 3];
    float4 o;
    o.x = fminf(fmaxf(y0.x - y2.x + acc.x + b0,  0.f), 6.f);
    o.y = fminf(fmaxf(y0.y - y2.y + acc.y + b1v, 0.f), 6.f);
    o.z = fminf(fmaxf(y0.z - y2.z + acc.z + b2v, 0.f), 6.f);
    o.w = fminf(fmaxf(y0.w - y2.w + acc.w + b3v, 0.f), 6.f);
    *(float4*)&g_H[(size_t)gw * 128 + (lane << 2)] = o;
}

// ---------------- layer 3 (128 -> 6 fused, then 2-wide props) ---------------
__global__ void k_gemm3(const float* __restrict__ W3) {
    __shared__ float ws[128 * 6];
    int tid = threadIdx.x;
    for (int idx = tid; idx < 768; idx += blockDim.x) {
        int i = idx / 6, c = idx % 6;
        ws[idx] = W3[(c >> 1) * 256 + i * 2 + (c & 1)];
    }
    __syncthreads();
    int node = blockIdx.x * blockDim.x + tid;
    if (node >= Nn) return;
    float acc[8] = {0, 0, 0, 0, 0, 0, 0, 0};
    const float* hr = &g_H[(size_t)node * 128];
    #pragma unroll 8
    for (int i = 0; i < 128; i++) {
        float h = hr[i];
        #pragma unroll
        for (int c = 0; c < 6; c++)
            acc[c] = fmaf(h, ws[i * 6 + c], acc[c]);
    }
    #pragma unroll
    for (int c = 0; c < 8; c++) g_Y3[node * 8 + c] = acc[c];
}

__global__ void k_propA3() {
    int i = blockIdx.x * blockDim.x + threadIdx.x;
    if (i >= Nn) return;
    int start = g_rowStart[i], d = g_deg[i];
    float a0 = 0.f, a1 = 0.f;
    for (int e = 0; e < d; e++) {
        int   c = __ldg(&g_csrCol[start + e]);
        float w = __ldg(&g_csrW[start + e]);
        a0 = fmaf(w, g_Y3[c * 8 + 4], a0);
        a1 = fmaf(w, g_Y3[c * 8 + 5], a1);
    }
    g_U2[i * 2]     = g_Y3[i * 8 + 2] + 2.f * a0;
    g_U2[i * 2 + 1] = g_Y3[i * 8 + 3] + 2.f * a1;
}

__global__ void k_propB3(const float* __restrict__ b3, float* __restrict__ out) {
    int i = blockIdx.x * blockDim.x + threadIdx.x;
    if (i >= Nn) return;
    int start = g_rowStart[i], d = g_deg[i];
    float a0 = 0.f, a1 = 0.f;
    for (int e = 0; e < d; e++) {
        int   c = __ldg(&g_csrCol[start + e]);
        float w = __ldg(&g_csrW[start + e]);
        a0 = fmaf(w, g_U2[c * 2],     a0);
        a1 = fmaf(w, g_U2[c * 2 + 1], a1);
    }
    out[i * 2]     = g_Y3[i * 8 + 0] - g_Y3[i * 8 + 4] + a0 + b3[0];
    out[i * 2 + 1] = g_Y3[i * 8 + 1] - g_Y3[i * 8 + 5] + a1 + b3[1];
}

// ---------------- output tail (edge_index passthrough) ----------------------
__global__ void k_tail_i64(long long* __restrict__ dst) {
    int i = blockIdx.x * blockDim.x + threadIdx.x;
    if (i < 2 * Ee) dst[i] = (long long)(i < Ee ? g_row[i] : g_col[i - Ee]);
}

__global__ void k_tail_f32(float* __restrict__ dst, int n) {
    int i = blockIdx.x * blockDim.x + threadIdx.x;
    if (i < n) dst[i] = (float)(i < Ee ? g_row[i] : g_col[i - Ee]);
}

// ---------------- launcher ---------------------------------------------------
extern "C" void kernel_launch(void* const* d_in, const int* in_sizes, int n_in,
                              void* d_out, int out_size) {
    const float* x  = (const float*)d_in[0];
    const void*  ei = d_in[1];
    const float* W1 = (const float*)d_in[2];
    const float* b1 = (const float*)d_in[3];
    const float* W2 = (const float*)d_in[4];
    const float* b2 = (const float*)d_in[5];
    const float* W3 = (const float*)d_in[6];
    const float* b3 = (const float*)d_in[7];

    const int gN = (Nn + 255) / 256;
    const int gE = (Ee + 255) / 256;
    const int gW = (Nn * 32 + 255) / 256;   // warp-per-node kernels
    dim3 gg((Nn + BM - 1) / BM, 384 / BN);  // (391, 3)

    // Order puts sgemm1 at process-launch index 5 (harness emits 2 first),
    // so ncu's skip-5 capture lands on the hot SGEMM.
    k_detect<<<1, 512>>>((const int*)ei);                       // idx 2
    k_zero_deg<<<gN, 256>>>();                                  // idx 3
    k_wcat<<<(FIN * 384 + 255) / 256, 256>>>(W1, FIN);          // idx 4
    k_sgemm_t<FIN, false><<<gg, 256>>>(x);                      // idx 5  <- ncu
    k_norm<<<gE, 256>>>(ei);                                    // (norm+count)

    // --- graph preprocessing: scan, dinv, CSR fill
    k_scan_blocks<<<49, 1024>>>();
    k_scan_partials<<<1, 64>>>(49);
    k_add_offsets<<<gN, 256>>>();
    k_fill<<<gE, 256>>>();

    // --- layer 1 props: H = relu6(Y0 - Y2 + P(Y1 + 2 P Y2) + b1)
    k_propA<<<gW, 256>>>();
    k_propB<<<gW, 256>>>(b1);

    // --- layer 2
    k_wcat<<<(HID * 384 + 255) / 256, 256>>>(W2, HID);
    k_sgemm_t<HID, true><<<gg, 256>>>(nullptr);
    k_propA<<<gW, 256>>>();
    k_propB<<<gW, 256>>>(b2);

    // --- layer 3 (no activation)
    k_gemm3<<<(Nn + 255) / 256, 256>>>(W3);
    k_propA3<<<gN, 256>>>();
    k_propB3<<<gN, 256>>>(b3, (float*)d_out);

    // --- edge_index passthrough into the tail of d_out, if present
    long long head = (long long)Nn * NCLS;            // 100000 fp32 elems
    long long tail = (long long)out_size - head;
    if (tail >= 2LL * 2 * Ee) {
        k_tail_i64<<<(2 * Ee + 255) / 256, 256>>>(
            (long long*)((float*)d_out + head));
    } else if (tail > 0) {
        int n = (int)(tail < 2LL * Ee ? tail : 2LL * Ee);
        k_tail_f32<<<(n + 255) / 256, 256>>>((float*)d_out + head, n);
    }
}